// round 4
// baseline (speedup 1.0000x reference)
#include <cuda_runtime.h>
#include <cuda_bf16.h>

// PointPillarsScatter gather v3:
//  - 128KB occupancy bitmap (L2-resident): empty 4-cell groups store zeros after ONE
//    L2-hit load (no DRAM-latency count/list chain for the 63% common case)
//  - 4 cells per thread -> all output stores are STG.128 (4x fewer store insts, 4x MLP)
//  - bitmap + counts self-clean inside gather (no memset nodes)
//
// Inputs:
//   d_in[0]: pillar_feats  float32 [B=4, P=30000, C=64]
//   d_in[1]: pillar_coords int32   [B=4, P=30000, 2]  (y, x)
// Output: float32 [4, 64, 512, 512]

#define BEV_H 512
#define BEV_W 512
#define HW (BEV_H * BEV_W)     // 262144 = 2^18
#define C_DIM 64
#define P_DIM 30000
#define B_DIM 4
#define CAP 8

__device__ unsigned int   d_bitmap[(B_DIM * HW) / 32];   // 128 KB, zero-init, self-cleaned
__device__ int            d_count[B_DIM * HW];           // 4 MB, zero-init, self-cleaned
__device__ unsigned short d_list[B_DIM * HW * CAP];      // 16 MB

__global__ void pp_build_kernel(const int* __restrict__ coords) {
    int p = blockIdx.x * blockDim.x + threadIdx.x;
    if (p >= B_DIM * P_DIM) return;

    int2 yx = reinterpret_cast<const int2*>(coords)[p];
    int y = min(max(yx.x, 0), BEV_H - 1);
    int x = min(max(yx.y, 0), BEV_W - 1);

    int b   = p / P_DIM;
    int pid = p - b * P_DIM;
    int idx = b * HW + y * BEV_W + x;

    int pos = atomicAdd(&d_count[idx], 1);
    if (pos < CAP) d_list[(size_t)idx * CAP + pos] = (unsigned short)pid;
    if (pos == 0) atomicOr(&d_bitmap[idx >> 5], 1u << (idx & 31));
}

__global__ __launch_bounds__(256) void pp_gather_kernel(const float* __restrict__ feats,
                                                        float* __restrict__ out) {
    int t = blockIdx.x * blockDim.x + threadIdx.x;   // 0 .. B*HW/4
    int idx0 = t << 2;                                // first of 4 consecutive cells
    int b     = idx0 >> 18;                           // HW = 2^18
    int cell0 = idx0 & (HW - 1);

    // One bitmap word covers 32 cells = 8 threads of this warp (aligned groups).
    unsigned wordIdx = (unsigned)idx0 >> 5;
    unsigned word = d_bitmap[wordIdx];
    // Same-warp: the load above executes for all 8 lanes before this store.
    if (word && (idx0 & 31) == 0) d_bitmap[wordIdx] = 0;

    unsigned mask = (word >> (idx0 & 31)) & 0xFu;

    int n0 = 0, n1 = 0, n2 = 0, n3 = 0;
    if (mask) {
        int4 cnt = *reinterpret_cast<const int4*>(&d_count[idx0]);
        *reinterpret_cast<int4*>(&d_count[idx0]) = make_int4(0, 0, 0, 0);
        n0 = min(cnt.x, CAP); n1 = min(cnt.y, CAP);
        n2 = min(cnt.z, CAP); n3 = min(cnt.w, CAP);
    }

    const float* fb = feats + (size_t)b * P_DIM * C_DIM;
    float* o = out + (size_t)b * C_DIM * HW + cell0;
    const unsigned short* lst = &d_list[(size_t)idx0 * CAP];

    // 16 chunks of 4 channels; per chunk: accumulate 4 cells, emit 4 float4 stores.
    #pragma unroll
    for (int c0 = 0; c0 < C_DIM; c0 += 4) {
        float a0x = 0.f, a0y = 0.f, a0z = 0.f, a0w = 0.f;
        float a1x = 0.f, a1y = 0.f, a1z = 0.f, a1w = 0.f;
        float a2x = 0.f, a2y = 0.f, a2z = 0.f, a2w = 0.f;
        float a3x = 0.f, a3y = 0.f, a3z = 0.f, a3w = 0.f;

        // Rare path: pid reloads are 2B L1-hit loads (list line cached after first chunk).
        for (int i = 0; i < n0; i++) {
            float4 f = *reinterpret_cast<const float4*>(fb + (size_t)lst[0 * CAP + i] * C_DIM + c0);
            a0x += f.x; a0y += f.y; a0z += f.z; a0w += f.w;
        }
        for (int i = 0; i < n1; i++) {
            float4 f = *reinterpret_cast<const float4*>(fb + (size_t)lst[1 * CAP + i] * C_DIM + c0);
            a1x += f.x; a1y += f.y; a1z += f.z; a1w += f.w;
        }
        for (int i = 0; i < n2; i++) {
            float4 f = *reinterpret_cast<const float4*>(fb + (size_t)lst[2 * CAP + i] * C_DIM + c0);
            a2x += f.x; a2y += f.y; a2z += f.z; a2w += f.w;
        }
        for (int i = 0; i < n3; i++) {
            float4 f = *reinterpret_cast<const float4*>(fb + (size_t)lst[3 * CAP + i] * C_DIM + c0);
            a3x += f.x; a3y += f.y; a3z += f.z; a3w += f.w;
        }

        float4 v0 = make_float4(a0x, a1x, a2x, a3x);
        float4 v1 = make_float4(a0y, a1y, a2y, a3y);
        float4 v2 = make_float4(a0z, a1z, a2z, a3z);
        float4 v3 = make_float4(a0w, a1w, a2w, a3w);
        __stcs(reinterpret_cast<float4*>(o + (size_t)(c0 + 0) * HW), v0);
        __stcs(reinterpret_cast<float4*>(o + (size_t)(c0 + 1) * HW), v1);
        __stcs(reinterpret_cast<float4*>(o + (size_t)(c0 + 2) * HW), v2);
        __stcs(reinterpret_cast<float4*>(o + (size_t)(c0 + 3) * HW), v3);
    }
}

extern "C" void kernel_launch(void* const* d_in, const int* in_sizes, int n_in,
                              void* d_out, int out_size) {
    const float* feats  = (const float*)d_in[0];
    const int*   coords = (const int*)d_in[1];
    float*       out    = (float*)d_out;

    int n_pillars = B_DIM * P_DIM;                 // 120,000
    pp_build_kernel<<<(n_pillars + 255) / 256, 256>>>(coords);

    int n_groups = (B_DIM * HW) / 4;               // 262,144 threads
    pp_gather_kernel<<<n_groups / 256, 256>>>(feats, out);
}